// round 4
// baseline (speedup 1.0000x reference)
#include <cuda_runtime.h>

// Problem constants (fixed by setup_inputs)
#define NN   65536      // total nodes
#define EIN  64         // input dim
#define HID  128        // hidden dim
#define NE   524288     // edges
#define NG   64         // graphs
#define NPG  1024       // nodes per graph
#define NLAY 3

typedef unsigned long long u64;

// ---------------- persistent device scratch ----------------
__device__ float g_x [NN * HID];   // current activations
__device__ float g_xi[NN * HID];   // layer "self" branch
__device__ float g_ui[NN * HID];   // layer "aggr" branch (pre-scatter)
__device__ float g_u [NN * HID];   // pure aggregation of last layer (pooling)
__device__ float g_ug[NG * HID];
__device__ float g_stats[2 * HID];   // [0:128) col-sum of x, [128:256) col-sumsq of x
__device__ float g_wf2[2 * HID * 2]; // BN-folded final weights [256][2]
__device__ float g_wfb[2];           // BN-folded final bias

// CSR (by destination node), rebuilt every launch
__device__ int g_cnt[NN + 1];    // counts -> row_ptr (in-place scan)
__device__ int g_cursor[NN];     // fill cursors
__device__ int g_col[NE];        // src node per edge, bucketed by dst

// ---------------- f32x2 packed-FMA helpers ----------------
__device__ __forceinline__ u64 pack2(float lo, float hi) {
    u64 r; asm("mov.b64 %0, {%1, %2};" : "=l"(r) : "f"(lo), "f"(hi)); return r;
}
__device__ __forceinline__ void unpack2(u64 v, float& lo, float& hi) {
    asm("mov.b64 {%0, %1}, %2;" : "=f"(lo), "=f"(hi) : "l"(v));
}
__device__ __forceinline__ u64 ffma2(u64 a, u64 b, u64 c) {
    u64 d; asm("fma.rn.f32x2 %0, %1, %2, %3;" : "=l"(d) : "l"(a), "l"(b), "l"(c)); return d;
}

// ================= CSR construction =================
__global__ __launch_bounds__(256) void zero_cnt_kernel() {
    const int i = blockIdx.x * 256 + threadIdx.x;
    if (i <= NN) g_cnt[i] = 0;
}

__global__ __launch_bounds__(256) void hist_kernel(const int* __restrict__ ei, int E) {
    const int e = blockIdx.x * 256 + threadIdx.x;
    if (e < E) atomicAdd(&g_cnt[__ldg(&ei[E + e])], 1);
}

// single block, 1024 threads, 64 entries each (NN = 1024*64)
__global__ __launch_bounds__(1024) void scan_kernel() {
    __shared__ int sp[1024];
    const int t = threadIdx.x;
    const int base = t * 64;
    int s = 0;
    #pragma unroll 8
    for (int j = 0; j < 64; j++) s += g_cnt[base + j];
    sp[t] = s;
    __syncthreads();
    #pragma unroll
    for (int off = 1; off < 1024; off <<= 1) {
        int v = (t >= off) ? sp[t - off] : 0;
        __syncthreads();
        sp[t] += v;
        __syncthreads();
    }
    int run = sp[t] - s;   // exclusive prefix
    #pragma unroll 8
    for (int j = 0; j < 64; j++) {
        const int c = g_cnt[base + j];
        g_cnt[base + j] = run;      // in-place: becomes row_ptr
        g_cursor[base + j] = run;
        run += c;
    }
    if (t == 1023) g_cnt[NN] = run;
}

__global__ __launch_bounds__(256) void fill_kernel(const int* __restrict__ ei, int E) {
    const int e = blockIdx.x * 256 + threadIdx.x;
    if (e >= E) return;
    const int src = __ldg(&ei[e]);
    const int dst = __ldg(&ei[E + e]);
    const int slot = atomicAdd(&g_cursor[dst], 1);
    g_col[slot] = src;
}

// ---------------- input projection: x = relu(x_in @ Wp + bp) ----------------
__global__ __launch_bounds__(256) void gemm_proj_kernel(
    const float* __restrict__ xin, const float* __restrict__ Wp,
    const float* __restrict__ bp)
{
    __shared__ float sW[EIN * HID];   // 32 KB
    __shared__ float sX[32 * EIN];    // 8 KB
    const int tid = threadIdx.x;
    const int w = tid >> 5, lane = tid & 31;

    for (int i = tid; i < EIN * HID / 4; i += 256)
        ((float4*)sW)[i] = ((const float4*)Wp)[i];

    const float b0 = bp[2 * lane],      b1 = bp[2 * lane + 1];
    const float b2 = bp[64 + 2 * lane], b3 = bp[65 + 2 * lane];

    for (int chunk = blockIdx.x; chunk < NN / 32; chunk += gridDim.x) {
        const int row0 = chunk * 32;
        __syncthreads();
        for (int i = tid; i < 32 * EIN / 4; i += 256)
            ((float4*)sX)[i] = ((const float4*)(xin + (size_t)row0 * EIN))[i];
        __syncthreads();

        u64 acc[4][2];
        #pragma unroll
        for (int r = 0; r < 4; r++) { acc[r][0] = 0ull; acc[r][1] = 0ull; }

        #pragma unroll
        for (int k = 0; k < EIN; k++) {
            const u64 w0 = *(const u64*)&sW[k * HID + 2 * lane];
            const u64 w1 = *(const u64*)&sW[k * HID + 64 + 2 * lane];
            #pragma unroll
            for (int r = 0; r < 4; r++) {
                const float xv = sX[(w * 4 + r) * EIN + k];
                const u64 xx = pack2(xv, xv);
                acc[r][0] = ffma2(xx, w0, acc[r][0]);
                acc[r][1] = ffma2(xx, w1, acc[r][1]);
            }
        }
        #pragma unroll
        for (int r = 0; r < 4; r++) {
            const int row = row0 + w * 4 + r;
            float2 o;
            unpack2(acc[r][0], o.x, o.y);
            o.x = fmaxf(o.x + b0, 0.f); o.y = fmaxf(o.y + b1, 0.f);
            *(float2*)&g_x[row * HID + 2 * lane] = o;
            unpack2(acc[r][1], o.x, o.y);
            o.x = fmaxf(o.x + b2, 0.f); o.y = fmaxf(o.y + b3, 0.f);
            *(float2*)&g_x[row * HID + 64 + 2 * lane] = o;
        }
    }
}

// ---------------- dual GEMM: xi = x@Wl + bl ; ui = x@Wa + ba ----------------
__global__ __launch_bounds__(256) void gemm_dual_kernel(
    const float* __restrict__ Wl, const float* __restrict__ bl,
    const float* __restrict__ Wa, const float* __restrict__ ba)
{
    extern __shared__ float smd[];
    float* sWl = smd;                    // 128*128
    float* sWa = smd + HID * HID;        // 128*128
    float* sX  = smd + 2 * HID * HID;    // 32*128

    const int tid = threadIdx.x;
    const int w = tid >> 5, lane = tid & 31;

    for (int i = tid; i < HID * HID / 4; i += 256) {
        ((float4*)sWl)[i] = ((const float4*)Wl)[i];
        ((float4*)sWa)[i] = ((const float4*)Wa)[i];
    }

    const float bl0 = bl[2 * lane],      bl1 = bl[2 * lane + 1];
    const float bl2 = bl[64 + 2 * lane], bl3 = bl[65 + 2 * lane];
    const float ba0 = ba[2 * lane],      ba1 = ba[2 * lane + 1];
    const float ba2 = ba[64 + 2 * lane], ba3 = ba[65 + 2 * lane];

    for (int chunk = blockIdx.x; chunk < NN / 32; chunk += gridDim.x) {
        const int row0 = chunk * 32;
        __syncthreads();
        for (int i = tid; i < 32 * HID / 4; i += 256)
            ((float4*)sX)[i] = ((const float4*)(g_x + (size_t)row0 * HID))[i];
        __syncthreads();

        u64 accl[4][2], acca[4][2];
        #pragma unroll
        for (int r = 0; r < 4; r++) {
            accl[r][0] = 0ull; accl[r][1] = 0ull;
            acca[r][0] = 0ull; acca[r][1] = 0ull;
        }

        #pragma unroll 8
        for (int k = 0; k < HID; k++) {
            const u64 wl0 = *(const u64*)&sWl[k * HID + 2 * lane];
            const u64 wl1 = *(const u64*)&sWl[k * HID + 64 + 2 * lane];
            const u64 wa0 = *(const u64*)&sWa[k * HID + 2 * lane];
            const u64 wa1 = *(const u64*)&sWa[k * HID + 64 + 2 * lane];
            #pragma unroll
            for (int r = 0; r < 4; r++) {
                const float xv = sX[(w * 4 + r) * HID + k];
                const u64 xx = pack2(xv, xv);
                accl[r][0] = ffma2(xx, wl0, accl[r][0]);
                accl[r][1] = ffma2(xx, wl1, accl[r][1]);
                acca[r][0] = ffma2(xx, wa0, acca[r][0]);
                acca[r][1] = ffma2(xx, wa1, acca[r][1]);
            }
        }
        #pragma unroll
        for (int r = 0; r < 4; r++) {
            const int row = row0 + w * 4 + r;
            float2 o;
            unpack2(accl[r][0], o.x, o.y); o.x += bl0; o.y += bl1;
            *(float2*)&g_xi[row * HID + 2 * lane] = o;
            unpack2(accl[r][1], o.x, o.y); o.x += bl2; o.y += bl3;
            *(float2*)&g_xi[row * HID + 64 + 2 * lane] = o;
            unpack2(acca[r][0], o.x, o.y); o.x += ba0; o.y += ba1;
            *(float2*)&g_ui[row * HID + 2 * lane] = o;
            unpack2(acca[r][1], o.x, o.y); o.x += ba2; o.y += ba3;
            *(float2*)&g_ui[row * HID + 64 + 2 * lane] = o;
        }
    }
}

// ---------------- CSR-gather aggregation + fused combine --------------------
// One warp per dst node: s = sum_{e in CSR[node]} ui[src_e];
// x[node] = relu(xi[node] + s); optionally u[node] = s (last layer, pooling).
__global__ __launch_bounds__(256) void aggregate_kernel(int store_u)
{
    const int warp = threadIdx.x >> 5, lane = threadIdx.x & 31;
    const int node = blockIdx.x * 8 + warp;       // grid = NN/8
    const int start = __ldg(&g_cnt[node]);
    const int end   = __ldg(&g_cnt[node + 1]);
    const int c = lane * 4;

    float4 a = make_float4(0.f, 0.f, 0.f, 0.f);
    float4 b = make_float4(0.f, 0.f, 0.f, 0.f);
    int e = start;
    for (; e + 2 <= end; e += 2) {
        const int s1 = __ldg(&g_col[e]);
        const int s2 = __ldg(&g_col[e + 1]);
        const float4 v1 = *(const float4*)&g_ui[s1 * HID + c];
        const float4 v2 = *(const float4*)&g_ui[s2 * HID + c];
        a.x += v1.x; a.y += v1.y; a.z += v1.z; a.w += v1.w;
        b.x += v2.x; b.y += v2.y; b.z += v2.z; b.w += v2.w;
    }
    if (e < end) {
        const int s1 = __ldg(&g_col[e]);
        const float4 v1 = *(const float4*)&g_ui[s1 * HID + c];
        a.x += v1.x; a.y += v1.y; a.z += v1.z; a.w += v1.w;
    }
    float4 s;
    s.x = a.x + b.x; s.y = a.y + b.y; s.z = a.z + b.z; s.w = a.w + b.w;

    if (store_u) *(float4*)&g_u[node * HID + c] = s;

    const float4 xi = *(const float4*)&g_xi[node * HID + c];
    float4 o;
    o.x = fmaxf(xi.x + s.x, 0.f);
    o.y = fmaxf(xi.y + s.y, 0.f);
    o.z = fmaxf(xi.z + s.z, 0.f);
    o.w = fmaxf(xi.w + s.w, 0.f);
    *(float4*)&g_x[node * HID + c] = o;
}

// ---------------- zero pooling/stats scratch ----------------
__global__ __launch_bounds__(256) void zero_aux_kernel() {
    const int i = blockIdx.x * 256 + threadIdx.x;   // 32 blocks -> 8192 threads
    if (i < NG * HID) g_ug[i] = 0.f;
    if (i < 2 * HID)  g_stats[i] = 0.f;
    if (i < 2)        g_wfb[i] = 0.f;
}

// ---------------- per-graph pooling: ug[g] = sum over nodes of u --------
__global__ __launch_bounds__(256) void graphsum_kernel() {
    const int g = blockIdx.x >> 2;
    const int chunk = blockIdx.x & 3;
    const int col = threadIdx.x & 127;
    const int half = threadIdx.x >> 7;
    const int base = g * NPG + chunk * 256 + half;
    float s = 0.f;
    #pragma unroll 8
    for (int r = 0; r < 256; r += 2)
        s += g_u[(base + r) * HID + col];
    atomicAdd(&g_ug[g * HID + col], s);
}

// ---------------- column stats of x (sum, sumsq) ----------------
__global__ __launch_bounds__(256) void stats_kernel() {
    const int col = threadIdx.x & 127;
    const int half = threadIdx.x >> 7;
    const int base = blockIdx.x * 256 + half;
    float s = 0.f, sq = 0.f;
    #pragma unroll 8
    for (int r = 0; r < 256; r += 2) {
        const float v = g_x[(base + r) * HID + col];
        s += v; sq += v * v;
    }
    atomicAdd(&g_stats[col], s);
    atomicAdd(&g_stats[HID + col], sq);
}

// ---------------- fold BatchNorm into final weights ----------------
__global__ __launch_bounds__(256) void fold_kernel(
    const float* __restrict__ gamma, const float* __restrict__ beta,
    const float* __restrict__ Wf, const float* __restrict__ bf)
{
    const int c = threadIdx.x;  // 256 channels
    float mean, var;
    if (c < HID) {
        const float s = g_stats[c], sq = g_stats[HID + c];
        mean = s * (1.f / NN);
        var = sq * (1.f / NN) - mean * mean;
    } else {
        // channels 128..255: graph-level stats of ug (two-pass, avoids E[x^2]-m^2
        // cancellation: ug values have mean >> std)
        float s = 0.f;
        for (int g = 0; g < NG; g++) s += g_ug[g * HID + (c - HID)];
        mean = s * (1.f / NG);
        float sq = 0.f;
        for (int g = 0; g < NG; g++) {
            const float d = g_ug[g * HID + (c - HID)] - mean;
            sq += d * d;
        }
        var = sq * (1.f / NG);
    }
    const float a = gamma[c] * rsqrtf(var + 1e-5f);
    const float sh = beta[c] - mean * a;
    const float w0 = Wf[2 * c], w1 = Wf[2 * c + 1];
    g_wf2[2 * c] = a * w0;
    g_wf2[2 * c + 1] = a * w1;
    atomicAdd(&g_wfb[0], sh * w0);
    atomicAdd(&g_wfb[1], sh * w1);
    if (c == 0) { atomicAdd(&g_wfb[0], bf[0]); atomicAdd(&g_wfb[1], bf[1]); }
}

// ---------------- final: out[r] = concat(x[r], ug[graph]) @ wf2 + wfb ----
__global__ __launch_bounds__(256) void final_kernel(float* __restrict__ out) {
    __shared__ float sw[2 * HID * 2 + 2];
    const int tid = threadIdx.x;
    sw[2 * tid] = g_wf2[2 * tid];
    sw[2 * tid + 1] = g_wf2[2 * tid + 1];
    if (tid < 2) sw[512 + tid] = g_wfb[tid];
    __syncthreads();

    const int warp = tid >> 5, lane = tid & 31;
    const int row = blockIdx.x * 8 + warp;   // NN/8 blocks
    const float* xr = g_x + (size_t)row * HID;
    const float* ur = g_ug + (size_t)(row >> 10) * HID;

    float a0 = 0.f, a1 = 0.f;
    #pragma unroll
    for (int j = 0; j < 4; j++) {
        const int c = lane + 32 * j;
        const float z = xr[c];
        a0 += z * sw[2 * c];
        a1 += z * sw[2 * c + 1];
    }
    #pragma unroll
    for (int j = 0; j < 4; j++) {
        const int c = lane + 32 * j;
        const float z = ur[c];
        a0 += z * sw[2 * (HID + c)];
        a1 += z * sw[2 * (HID + c) + 1];
    }
    #pragma unroll
    for (int off = 16; off > 0; off >>= 1) {
        a0 += __shfl_xor_sync(0xffffffffu, a0, off);
        a1 += __shfl_xor_sync(0xffffffffu, a1, off);
    }
    if (lane == 0) {
        out[row * 2]     = a0 + sw[512];
        out[row * 2 + 1] = a1 + sw[513];
    }
}

// ---------------- launch ----------------
extern "C" void kernel_launch(void* const* d_in, const int* in_sizes, int n_in,
                              void* d_out, int out_size)
{
    const float* x_in  = (const float*)d_in[0];
    const int*   ei    = (const int*)  d_in[1];
    // d_in[2] = n_nodes (constant 1024, hardcoded)
    const float* Wp    = (const float*)d_in[3];
    const float* bp    = (const float*)d_in[4];
    const float* Wl    = (const float*)d_in[5];
    const float* bl    = (const float*)d_in[6];
    const float* Wa    = (const float*)d_in[7];
    const float* ba    = (const float*)d_in[8];
    const float* gamma = (const float*)d_in[9];
    const float* beta  = (const float*)d_in[10];
    const float* Wf    = (const float*)d_in[11];
    const float* bf    = (const float*)d_in[12];
    float* out = (float*)d_out;

    const int E = in_sizes[1] / 2;

    const int SMEM_DUAL = (2 * HID * HID + 32 * HID) * (int)sizeof(float); // 147456
    cudaFuncSetAttribute(gemm_dual_kernel,
                         cudaFuncAttributeMaxDynamicSharedMemorySize, SMEM_DUAL);

    // CSR build (once per launch)
    zero_cnt_kernel<<<(NN + 256) / 256, 256>>>();
    hist_kernel<<<(E + 255) / 256, 256>>>(ei, E);
    scan_kernel<<<1, 1024>>>();
    fill_kernel<<<(E + 255) / 256, 256>>>(ei, E);

    gemm_proj_kernel<<<148, 256>>>(x_in, Wp, bp);

    for (int i = 0; i < NLAY; i++) {
        gemm_dual_kernel<<<148, 256, SMEM_DUAL>>>(
            Wl + i * HID * HID, bl + i * HID,
            Wa + i * HID * HID, ba + i * HID);
        aggregate_kernel<<<NN / 8, 256>>>(i == NLAY - 1 ? 1 : 0);
    }

    zero_aux_kernel<<<32, 256>>>();
    graphsum_kernel<<<NG * 4, 256>>>();
    stats_kernel<<<NN / 256, 256>>>();
    fold_kernel<<<1, 256>>>(gamma, beta, Wf, bf);
    final_kernel<<<NN / 8, 256>>>(out);
}

// round 5
// speedup vs baseline: 1.0527x; 1.0527x over previous
#include <cuda_runtime.h>

// Problem constants (fixed by setup_inputs)
#define NN   65536      // total nodes
#define EIN  64         // input dim
#define HID  128        // hidden dim
#define NE   524288     // edges
#define NG   64         // graphs
#define NPG  1024       // nodes per graph
#define NLAY 3

typedef unsigned long long u64;

// ---------------- persistent device scratch ----------------
__device__ float g_x [NN * HID];   // current activations
__device__ float g_xi[NN * HID];   // last layer's self branch (for u recovery)
__device__ float g_ui[NN * HID];   // aggr branch (pre-scatter)
__device__ float g_u [NN * HID];   // scatter target, initialized with xi
__device__ float g_ug[NG * HID];
__device__ float g_stats[2 * HID];   // [0:128) col-sum of x, [128:256) col-sumsq
__device__ float g_wf2[2 * HID * 2]; // BN-folded final weights [256][2]
__device__ float g_wfb[2];           // BN-folded final bias

// ---------------- f32x2 packed-FMA helpers ----------------
__device__ __forceinline__ u64 pack2(float lo, float hi) {
    u64 r; asm("mov.b64 %0, {%1, %2};" : "=l"(r) : "f"(lo), "f"(hi)); return r;
}
__device__ __forceinline__ void unpack2(u64 v, float& lo, float& hi) {
    asm("mov.b64 {%0, %1}, %2;" : "=f"(lo), "=f"(hi) : "l"(v));
}
__device__ __forceinline__ u64 ffma2(u64 a, u64 b, u64 c) {
    u64 d; asm("fma.rn.f32x2 %0, %1, %2, %3;" : "=l"(d) : "l"(a), "l"(b), "l"(c)); return d;
}

// ---------------- input projection: x = relu(x_in @ Wp + bp) ----------------
__global__ __launch_bounds__(256) void gemm_proj_kernel(
    const float* __restrict__ xin, const float* __restrict__ Wp,
    const float* __restrict__ bp)
{
    __shared__ float sW[EIN * HID];   // 32 KB
    __shared__ float sX[32 * EIN];    // 8 KB
    const int tid = threadIdx.x;
    const int w = tid >> 5, lane = tid & 31;

    for (int i = tid; i < EIN * HID / 4; i += 256)
        ((float4*)sW)[i] = ((const float4*)Wp)[i];

    const float b0 = bp[2 * lane],      b1 = bp[2 * lane + 1];
    const float b2 = bp[64 + 2 * lane], b3 = bp[65 + 2 * lane];

    for (int chunk = blockIdx.x; chunk < NN / 32; chunk += gridDim.x) {
        const int row0 = chunk * 32;
        __syncthreads();
        for (int i = tid; i < 32 * EIN / 4; i += 256)
            ((float4*)sX)[i] = ((const float4*)(xin + (size_t)row0 * EIN))[i];
        __syncthreads();

        u64 acc[4][2];
        #pragma unroll
        for (int r = 0; r < 4; r++) { acc[r][0] = 0ull; acc[r][1] = 0ull; }

        #pragma unroll
        for (int k = 0; k < EIN; k++) {
            const u64 w0 = *(const u64*)&sW[k * HID + 2 * lane];
            const u64 w1 = *(const u64*)&sW[k * HID + 64 + 2 * lane];
            #pragma unroll
            for (int r = 0; r < 4; r++) {
                const float xv = sX[(w * 4 + r) * EIN + k];
                const u64 xx = pack2(xv, xv);
                acc[r][0] = ffma2(xx, w0, acc[r][0]);
                acc[r][1] = ffma2(xx, w1, acc[r][1]);
            }
        }
        #pragma unroll
        for (int r = 0; r < 4; r++) {
            const int row = row0 + w * 4 + r;
            float2 o;
            unpack2(acc[r][0], o.x, o.y);
            o.x = fmaxf(o.x + b0, 0.f); o.y = fmaxf(o.y + b1, 0.f);
            *(float2*)&g_x[row * HID + 2 * lane] = o;
            unpack2(acc[r][1], o.x, o.y);
            o.x = fmaxf(o.x + b2, 0.f); o.y = fmaxf(o.y + b3, 0.f);
            *(float2*)&g_x[row * HID + 64 + 2 * lane] = o;
        }
    }
}

// ---------------- dual GEMM ----------------
// g_u  := x@Wl + bl   (scatter init = self branch)
// g_ui := x@Wa + ba   (aggregation messages)
// last layer only: also g_xi := x@Wl + bl  (for pooled-u recovery)
__global__ __launch_bounds__(256) void gemm_dual_kernel(
    const float* __restrict__ Wl, const float* __restrict__ bl,
    const float* __restrict__ Wa, const float* __restrict__ ba,
    int save_xi)
{
    extern __shared__ float smd[];
    float* sWl = smd;                    // 128*128
    float* sWa = smd + HID * HID;        // 128*128
    float* sX  = smd + 2 * HID * HID;    // 32*128

    const int tid = threadIdx.x;
    const int w = tid >> 5, lane = tid & 31;

    for (int i = tid; i < HID * HID / 4; i += 256) {
        ((float4*)sWl)[i] = ((const float4*)Wl)[i];
        ((float4*)sWa)[i] = ((const float4*)Wa)[i];
    }

    const float bl0 = bl[2 * lane],      bl1 = bl[2 * lane + 1];
    const float bl2 = bl[64 + 2 * lane], bl3 = bl[65 + 2 * lane];
    const float ba0 = ba[2 * lane],      ba1 = ba[2 * lane + 1];
    const float ba2 = ba[64 + 2 * lane], ba3 = ba[65 + 2 * lane];

    for (int chunk = blockIdx.x; chunk < NN / 32; chunk += gridDim.x) {
        const int row0 = chunk * 32;
        __syncthreads();
        for (int i = tid; i < 32 * HID / 4; i += 256)
            ((float4*)sX)[i] = ((const float4*)(g_x + (size_t)row0 * HID))[i];
        __syncthreads();

        u64 accl[4][2], acca[4][2];
        #pragma unroll
        for (int r = 0; r < 4; r++) {
            accl[r][0] = 0ull; accl[r][1] = 0ull;
            acca[r][0] = 0ull; acca[r][1] = 0ull;
        }

        #pragma unroll 8
        for (int k = 0; k < HID; k++) {
            const u64 wl0 = *(const u64*)&sWl[k * HID + 2 * lane];
            const u64 wl1 = *(const u64*)&sWl[k * HID + 64 + 2 * lane];
            const u64 wa0 = *(const u64*)&sWa[k * HID + 2 * lane];
            const u64 wa1 = *(const u64*)&sWa[k * HID + 64 + 2 * lane];
            #pragma unroll
            for (int r = 0; r < 4; r++) {
                const float xv = sX[(w * 4 + r) * HID + k];
                const u64 xx = pack2(xv, xv);
                accl[r][0] = ffma2(xx, wl0, accl[r][0]);
                accl[r][1] = ffma2(xx, wl1, accl[r][1]);
                acca[r][0] = ffma2(xx, wa0, acca[r][0]);
                acca[r][1] = ffma2(xx, wa1, acca[r][1]);
            }
        }
        #pragma unroll
        for (int r = 0; r < 4; r++) {
            const int row = row0 + w * 4 + r;
            float2 o;
            unpack2(accl[r][0], o.x, o.y); o.x += bl0; o.y += bl1;
            *(float2*)&g_u[row * HID + 2 * lane] = o;
            if (save_xi) *(float2*)&g_xi[row * HID + 2 * lane] = o;
            unpack2(accl[r][1], o.x, o.y); o.x += bl2; o.y += bl3;
            *(float2*)&g_u[row * HID + 64 + 2 * lane] = o;
            if (save_xi) *(float2*)&g_xi[row * HID + 64 + 2 * lane] = o;
            unpack2(acca[r][0], o.x, o.y); o.x += ba0; o.y += ba1;
            *(float2*)&g_ui[row * HID + 2 * lane] = o;
            unpack2(acca[r][1], o.x, o.y); o.x += ba2; o.y += ba3;
            *(float2*)&g_ui[row * HID + 64 + 2 * lane] = o;
        }
    }
}

// ---------------- edge scatter: u[dst] += ui[src] (vectorized red) --------
__global__ __launch_bounds__(256) void scatter_kernel(const int* __restrict__ ei, int E)
{
    const int idx = blockIdx.x * 256 + threadIdx.x; // E*32 threads
    const int e = idx >> 5;
    if (e >= E) return;
    const int c = (idx & 31) * 4;
    const int src = __ldg(&ei[e]);
    const int dst = __ldg(&ei[E + e]);
    const float4 v = *(const float4*)&g_ui[src * HID + c];
    float* p = &g_u[dst * HID + c];
    asm volatile("red.global.add.v4.f32 [%0], {%1, %2, %3, %4};"
                 :: "l"(p), "f"(v.x), "f"(v.y), "f"(v.z), "f"(v.w) : "memory");
}

// ---------------- combine: x = relu(u)  (u already contains xi + aggr) ----
__global__ __launch_bounds__(256) void combine_kernel() {
    const int i = blockIdx.x * 256 + threadIdx.x;   // NN*HID/4 threads
    const float4 t = ((const float4*)g_u)[i];
    float4 o;
    o.x = fmaxf(t.x, 0.f);
    o.y = fmaxf(t.y, 0.f);
    o.z = fmaxf(t.z, 0.f);
    o.w = fmaxf(t.w, 0.f);
    ((float4*)g_x)[i] = o;
}

// ---------------- last layer: combine + column stats fused ----------------
// x = relu(u); accumulate col-sum and col-sumsq of x into g_stats.
__global__ __launch_bounds__(256) void combine_stats_kernel() {
    const int col = threadIdx.x & 127;
    const int half = threadIdx.x >> 7;
    const int base = blockIdx.x * 256 + half;      // 256 blocks x 256 rows
    float s = 0.f, sq = 0.f;
    #pragma unroll 8
    for (int r = 0; r < 256; r += 2) {
        const float t = g_u[(base + r) * HID + col];
        const float v = fmaxf(t, 0.f);
        g_x[(base + r) * HID + col] = v;
        s += v; sq += v * v;
    }
    atomicAdd(&g_stats[col], s);
    atomicAdd(&g_stats[HID + col], sq);
}

// ---------------- zero pooling/stats scratch ----------------
__global__ __launch_bounds__(256) void zero_aux_kernel() {
    const int i = blockIdx.x * 256 + threadIdx.x;   // 32 blocks -> 8192 threads
    if (i < NG * HID) g_ug[i] = 0.f;
    if (i < 2 * HID)  g_stats[i] = 0.f;
    if (i < 2)        g_wfb[i] = 0.f;
}

// ---------------- per-graph pooling: ug[g] = sum over nodes of (u - xi) ---
__global__ __launch_bounds__(256) void graphsum_kernel() {
    const int g = blockIdx.x >> 2;
    const int chunk = blockIdx.x & 3;
    const int col = threadIdx.x & 127;
    const int half = threadIdx.x >> 7;
    const int base = g * NPG + chunk * 256 + half;
    float s = 0.f;
    #pragma unroll 8
    for (int r = 0; r < 256; r += 2) {
        const int idx = (base + r) * HID + col;
        s += g_u[idx] - g_xi[idx];
    }
    atomicAdd(&g_ug[g * HID + col], s);
}

// ---------------- fold BatchNorm into final weights ----------------
__global__ __launch_bounds__(256) void fold_kernel(
    const float* __restrict__ gamma, const float* __restrict__ beta,
    const float* __restrict__ Wf, const float* __restrict__ bf)
{
    const int c = threadIdx.x;  // 256 channels
    float mean, var;
    if (c < HID) {
        const float s = g_stats[c], sq = g_stats[HID + c];
        mean = s * (1.f / NN);
        var = sq * (1.f / NN) - mean * mean;
    } else {
        // channels 128..255: graph-level stats of ug, two-pass (avoids
        // E[x^2]-m^2 cancellation: ug values have mean >> std)
        float s = 0.f;
        for (int g = 0; g < NG; g++) s += g_ug[g * HID + (c - HID)];
        mean = s * (1.f / NG);
        float sq = 0.f;
        for (int g = 0; g < NG; g++) {
            const float d = g_ug[g * HID + (c - HID)] - mean;
            sq += d * d;
        }
        var = sq * (1.f / NG);
    }
    const float a = gamma[c] * rsqrtf(var + 1e-5f);
    const float sh = beta[c] - mean * a;
    const float w0 = Wf[2 * c], w1 = Wf[2 * c + 1];
    g_wf2[2 * c] = a * w0;
    g_wf2[2 * c + 1] = a * w1;
    atomicAdd(&g_wfb[0], sh * w0);
    atomicAdd(&g_wfb[1], sh * w1);
    if (c == 0) { atomicAdd(&g_wfb[0], bf[0]); atomicAdd(&g_wfb[1], bf[1]); }
}

// ---------------- final: out[r] = concat(x[r], ug[graph]) @ wf2 + wfb ----
__global__ __launch_bounds__(256) void final_kernel(float* __restrict__ out) {
    __shared__ float sw[2 * HID * 2 + 2];
    const int tid = threadIdx.x;
    sw[2 * tid] = g_wf2[2 * tid];
    sw[2 * tid + 1] = g_wf2[2 * tid + 1];
    if (tid < 2) sw[512 + tid] = g_wfb[tid];
    __syncthreads();

    const int warp = tid >> 5, lane = tid & 31;
    const int row = blockIdx.x * 8 + warp;   // NN/8 blocks
    const float* xr = g_x + (size_t)row * HID;
    const float* ur = g_ug + (size_t)(row >> 10) * HID;

    float a0 = 0.f, a1 = 0.f;
    #pragma unroll
    for (int j = 0; j < 4; j++) {
        const int c = lane + 32 * j;
        const float z = xr[c];
        a0 += z * sw[2 * c];
        a1 += z * sw[2 * c + 1];
    }
    #pragma unroll
    for (int j = 0; j < 4; j++) {
        const int c = lane + 32 * j;
        const float z = ur[c];
        a0 += z * sw[2 * (HID + c)];
        a1 += z * sw[2 * (HID + c) + 1];
    }
    #pragma unroll
    for (int off = 16; off > 0; off >>= 1) {
        a0 += __shfl_xor_sync(0xffffffffu, a0, off);
        a1 += __shfl_xor_sync(0xffffffffu, a1, off);
    }
    if (lane == 0) {
        out[row * 2]     = a0 + sw[512];
        out[row * 2 + 1] = a1 + sw[513];
    }
}

// ---------------- launch ----------------
extern "C" void kernel_launch(void* const* d_in, const int* in_sizes, int n_in,
                              void* d_out, int out_size)
{
    const float* x_in  = (const float*)d_in[0];
    const int*   ei    = (const int*)  d_in[1];
    // d_in[2] = n_nodes (constant 1024, hardcoded)
    const float* Wp    = (const float*)d_in[3];
    const float* bp    = (const float*)d_in[4];
    const float* Wl    = (const float*)d_in[5];
    const float* bl    = (const float*)d_in[6];
    const float* Wa    = (const float*)d_in[7];
    const float* ba    = (const float*)d_in[8];
    const float* gamma = (const float*)d_in[9];
    const float* beta  = (const float*)d_in[10];
    const float* Wf    = (const float*)d_in[11];
    const float* bf    = (const float*)d_in[12];
    float* out = (float*)d_out;

    const int E = in_sizes[1] / 2;

    const int SMEM_DUAL = (2 * HID * HID + 32 * HID) * (int)sizeof(float); // 147456
    cudaFuncSetAttribute(gemm_dual_kernel,
                         cudaFuncAttributeMaxDynamicSharedMemorySize, SMEM_DUAL);

    zero_aux_kernel<<<32, 256>>>();
    gemm_proj_kernel<<<148, 256>>>(x_in, Wp, bp);

    for (int i = 0; i < NLAY; i++) {
        const int last = (i == NLAY - 1);
        gemm_dual_kernel<<<148, 256, SMEM_DUAL>>>(
            Wl + i * HID * HID, bl + i * HID,
            Wa + i * HID * HID, ba + i * HID, last);
        scatter_kernel<<<(E * 32 + 255) / 256, 256>>>(ei, E);
        if (!last)
            combine_kernel<<<NN * HID / 4 / 256, 256>>>();
        else
            combine_stats_kernel<<<NN / 256, 256>>>();
    }

    graphsum_kernel<<<NG * 4, 256>>>();
    fold_kernel<<<1, 256>>>(gamma, beta, Wf, bf);
    final_kernel<<<NN / 8, 256>>>(out);
}

// round 6
// speedup vs baseline: 1.2201x; 1.1590x over previous
#include <cuda_runtime.h>

// Problem constants (fixed by setup_inputs)
#define NN   65536      // total nodes
#define EIN  64         // input dim
#define HID  128        // hidden dim
#define NE   524288     // edges
#define NG   64         // graphs
#define NPG  1024       // nodes per graph
#define NLAY 3

typedef unsigned long long u64;

// ---------------- persistent device scratch ----------------
__device__ float g_x [NN * HID];   // current activations
__device__ float g_xi[NN * HID];   // self branch
__device__ float g_ui[NN * HID];   // aggr branch (messages)
__device__ float g_u [NN * HID];   // last layer's aggregation (pooling)
__device__ float g_ug[NG * HID];
__device__ float g_stats[2 * HID];   // [0:128) col-sum of x, [128:256) col-sumsq
__device__ float g_wf2[2 * HID * 2]; // BN-folded final weights [256][2]
__device__ float g_wfb[2];           // BN-folded final bias

// CSR (by destination node), rebuilt every launch
__device__ int g_cnt[NN + 1];    // counts -> row_ptr
__device__ int g_cursor[NN];     // fill cursors
__device__ int g_col[NE];        // src node per edge, bucketed by dst
__device__ int g_part[64];       // block partial sums -> exclusive prefixes

// ---------------- f32x2 packed-FMA helpers ----------------
__device__ __forceinline__ u64 pack2(float lo, float hi) {
    u64 r; asm("mov.b64 %0, {%1, %2};" : "=l"(r) : "f"(lo), "f"(hi)); return r;
}
__device__ __forceinline__ void unpack2(u64 v, float& lo, float& hi) {
    asm("mov.b64 {%0, %1}, %2;" : "=f"(lo), "=f"(hi) : "l"(v));
}
__device__ __forceinline__ u64 ffma2(u64 a, u64 b, u64 c) {
    u64 d; asm("fma.rn.f32x2 %0, %1, %2, %3;" : "=l"(d) : "l"(a), "l"(b), "l"(c)); return d;
}

// ================= CSR construction (coalesced 3-stage scan) =================
__global__ __launch_bounds__(256) void zero_cnt_kernel() {   // 64 blocks
    ((int4*)g_cnt)[blockIdx.x * 256 + threadIdx.x] = make_int4(0, 0, 0, 0);
}

__global__ __launch_bounds__(256) void hist_kernel(const int* __restrict__ ei, int E) {
    const int e = blockIdx.x * 256 + threadIdx.x;
    if (e < E) atomicAdd(&g_cnt[__ldg(&ei[E + e])], 1);
}

// 64 blocks: each sums 1024 contiguous counts (coalesced int4)
__global__ __launch_bounds__(256) void partsum_kernel() {
    __shared__ int red[256];
    const int4 v = ((const int4*)g_cnt)[blockIdx.x * 256 + threadIdx.x];
    red[threadIdx.x] = v.x + v.y + v.z + v.w;
    __syncthreads();
    for (int off = 128; off > 0; off >>= 1) {
        if (threadIdx.x < off) red[threadIdx.x] += red[threadIdx.x + off];
        __syncthreads();
    }
    if (threadIdx.x == 0) g_part[blockIdx.x] = red[0];
}

// 1 block, 64 threads: exclusive scan of the 64 partials
__global__ __launch_bounds__(64) void scanpart_kernel() {
    __shared__ int sp[64];
    const int t = threadIdx.x;
    const int v = g_part[t];
    sp[t] = v;
    __syncthreads();
    for (int off = 1; off < 64; off <<= 1) {
        const int u = (t >= off) ? sp[t - off] : 0;
        __syncthreads();
        sp[t] += u;
        __syncthreads();
    }
    g_part[t] = sp[t] - v;            // exclusive prefix
    if (t == 63) g_cnt[NN] = sp[63];  // total edge count
}

// 64 blocks: local exclusive scan over 1024 counts, write row_ptr + cursor
__global__ __launch_bounds__(256) void localscan_kernel() {
    __shared__ int wsum[8];
    const int b = blockIdx.x, t = threadIdx.x;
    const int w = t >> 5, lane = t & 31;
    const int4 c = ((const int4*)g_cnt)[b * 256 + t];
    const int ts = c.x + c.y + c.z + c.w;
    int incl = ts;
    #pragma unroll
    for (int off = 1; off < 32; off <<= 1) {
        const int u = __shfl_up_sync(0xffffffffu, incl, off);
        if (lane >= off) incl += u;
    }
    if (lane == 31) wsum[w] = incl;
    __syncthreads();
    if (t == 0) {
        int run = 0;
        #pragma unroll
        for (int i = 0; i < 8; i++) { const int tmp = wsum[i]; wsum[i] = run; run += tmp; }
    }
    __syncthreads();
    const int base = g_part[b] + wsum[w] + (incl - ts);
    int4 r;
    r.x = base; r.y = r.x + c.x; r.z = r.y + c.y; r.w = r.z + c.z;
    ((int4*)g_cnt)[b * 256 + t] = r;
    ((int4*)g_cursor)[b * 256 + t] = r;
}

__global__ __launch_bounds__(256) void fill_kernel(const int* __restrict__ ei, int E) {
    const int e = blockIdx.x * 256 + threadIdx.x;
    if (e >= E) return;
    const int src = __ldg(&ei[e]);
    const int dst = __ldg(&ei[E + e]);
    const int slot = atomicAdd(&g_cursor[dst], 1);
    g_col[slot] = src;
}

// ---------------- input projection: x = relu(x_in @ Wp + bp) ----------------
__global__ __launch_bounds__(256) void gemm_proj_kernel(
    const float* __restrict__ xin, const float* __restrict__ Wp,
    const float* __restrict__ bp)
{
    __shared__ float sW[EIN * HID];   // 32 KB
    __shared__ float sX[32 * EIN];    // 8 KB
    const int tid = threadIdx.x;
    const int w = tid >> 5, lane = tid & 31;

    for (int i = tid; i < EIN * HID / 4; i += 256)
        ((float4*)sW)[i] = ((const float4*)Wp)[i];

    const float b0 = bp[2 * lane],      b1 = bp[2 * lane + 1];
    const float b2 = bp[64 + 2 * lane], b3 = bp[65 + 2 * lane];

    for (int chunk = blockIdx.x; chunk < NN / 32; chunk += gridDim.x) {
        const int row0 = chunk * 32;
        __syncthreads();
        for (int i = tid; i < 32 * EIN / 4; i += 256)
            ((float4*)sX)[i] = ((const float4*)(xin + (size_t)row0 * EIN))[i];
        __syncthreads();

        u64 acc[4][2];
        #pragma unroll
        for (int r = 0; r < 4; r++) { acc[r][0] = 0ull; acc[r][1] = 0ull; }

        #pragma unroll
        for (int k = 0; k < EIN; k++) {
            const u64 w0 = *(const u64*)&sW[k * HID + 2 * lane];
            const u64 w1 = *(const u64*)&sW[k * HID + 64 + 2 * lane];
            #pragma unroll
            for (int r = 0; r < 4; r++) {
                const float xv = sX[(w * 4 + r) * EIN + k];
                const u64 xx = pack2(xv, xv);
                acc[r][0] = ffma2(xx, w0, acc[r][0]);
                acc[r][1] = ffma2(xx, w1, acc[r][1]);
            }
        }
        #pragma unroll
        for (int r = 0; r < 4; r++) {
            const int row = row0 + w * 4 + r;
            float2 o;
            unpack2(acc[r][0], o.x, o.y);
            o.x = fmaxf(o.x + b0, 0.f); o.y = fmaxf(o.y + b1, 0.f);
            *(float2*)&g_x[row * HID + 2 * lane] = o;
            unpack2(acc[r][1], o.x, o.y);
            o.x = fmaxf(o.x + b2, 0.f); o.y = fmaxf(o.y + b3, 0.f);
            *(float2*)&g_x[row * HID + 64 + 2 * lane] = o;
        }
    }
}

// ---------------- dual GEMM: xi = x@Wl + bl ; ui = x@Wa + ba ----------------
__global__ __launch_bounds__(256) void gemm_dual_kernel(
    const float* __restrict__ Wl, const float* __restrict__ bl,
    const float* __restrict__ Wa, const float* __restrict__ ba)
{
    extern __shared__ float smd[];
    float* sWl = smd;                    // 128*128
    float* sWa = smd + HID * HID;        // 128*128
    float* sX  = smd + 2 * HID * HID;    // 32*128

    const int tid = threadIdx.x;
    const int w = tid >> 5, lane = tid & 31;

    for (int i = tid; i < HID * HID / 4; i += 256) {
        ((float4*)sWl)[i] = ((const float4*)Wl)[i];
        ((float4*)sWa)[i] = ((const float4*)Wa)[i];
    }

    const float bl0 = bl[2 * lane],      bl1 = bl[2 * lane + 1];
    const float bl2 = bl[64 + 2 * lane], bl3 = bl[65 + 2 * lane];
    const float ba0 = ba[2 * lane],      ba1 = ba[2 * lane + 1];
    const float ba2 = ba[64 + 2 * lane], ba3 = ba[65 + 2 * lane];

    for (int chunk = blockIdx.x; chunk < NN / 32; chunk += gridDim.x) {
        const int row0 = chunk * 32;
        __syncthreads();
        for (int i = tid; i < 32 * HID / 4; i += 256)
            ((float4*)sX)[i] = ((const float4*)(g_x + (size_t)row0 * HID))[i];
        __syncthreads();

        u64 accl[4][2], acca[4][2];
        #pragma unroll
        for (int r = 0; r < 4; r++) {
            accl[r][0] = 0ull; accl[r][1] = 0ull;
            acca[r][0] = 0ull; acca[r][1] = 0ull;
        }

        #pragma unroll 8
        for (int k = 0; k < HID; k++) {
            const u64 wl0 = *(const u64*)&sWl[k * HID + 2 * lane];
            const u64 wl1 = *(const u64*)&sWl[k * HID + 64 + 2 * lane];
            const u64 wa0 = *(const u64*)&sWa[k * HID + 2 * lane];
            const u64 wa1 = *(const u64*)&sWa[k * HID + 64 + 2 * lane];
            #pragma unroll
            for (int r = 0; r < 4; r++) {
                const float xv = sX[(w * 4 + r) * HID + k];
                const u64 xx = pack2(xv, xv);
                accl[r][0] = ffma2(xx, wl0, accl[r][0]);
                accl[r][1] = ffma2(xx, wl1, accl[r][1]);
                acca[r][0] = ffma2(xx, wa0, acca[r][0]);
                acca[r][1] = ffma2(xx, wa1, acca[r][1]);
            }
        }
        #pragma unroll
        for (int r = 0; r < 4; r++) {
            const int row = row0 + w * 4 + r;
            float2 o;
            unpack2(accl[r][0], o.x, o.y); o.x += bl0; o.y += bl1;
            *(float2*)&g_xi[row * HID + 2 * lane] = o;
            unpack2(accl[r][1], o.x, o.y); o.x += bl2; o.y += bl3;
            *(float2*)&g_xi[row * HID + 64 + 2 * lane] = o;
            unpack2(acca[r][0], o.x, o.y); o.x += ba0; o.y += ba1;
            *(float2*)&g_ui[row * HID + 2 * lane] = o;
            unpack2(acca[r][1], o.x, o.y); o.x += ba2; o.y += ba3;
            *(float2*)&g_ui[row * HID + 64 + 2 * lane] = o;
        }
    }
}

// ---------------- CSR-gather aggregation + fused combine (MLP=4) -----------
// One warp per dst node. 4 independent index loads -> 4 independent row
// gathers -> 4 accumulators, so ~4 loads are in flight per warp.
// x[node] = relu(xi[node] + s);  last layer also stores u[node] = s.
__global__ __launch_bounds__(256) void aggregate_kernel(int store_u)
{
    const int warp = threadIdx.x >> 5, lane = threadIdx.x & 31;
    const int node = blockIdx.x * 8 + warp;       // grid = NN/8
    const int start = __ldg(&g_cnt[node]);
    const int end   = __ldg(&g_cnt[node + 1]);
    const int c = lane * 4;

    float4 a0 = make_float4(0.f, 0.f, 0.f, 0.f);
    float4 a1 = make_float4(0.f, 0.f, 0.f, 0.f);
    float4 a2 = make_float4(0.f, 0.f, 0.f, 0.f);
    float4 a3 = make_float4(0.f, 0.f, 0.f, 0.f);

    int e = start;
    for (; e + 4 <= end; e += 4) {
        const int s0 = __ldg(&g_col[e]);
        const int s1 = __ldg(&g_col[e + 1]);
        const int s2 = __ldg(&g_col[e + 2]);
        const int s3 = __ldg(&g_col[e + 3]);
        const float4 v0 = *(const float4*)&g_ui[s0 * HID + c];
        const float4 v1 = *(const float4*)&g_ui[s1 * HID + c];
        const float4 v2 = *(const float4*)&g_ui[s2 * HID + c];
        const float4 v3 = *(const float4*)&g_ui[s3 * HID + c];
        a0.x += v0.x; a0.y += v0.y; a0.z += v0.z; a0.w += v0.w;
        a1.x += v1.x; a1.y += v1.y; a1.z += v1.z; a1.w += v1.w;
        a2.x += v2.x; a2.y += v2.y; a2.z += v2.z; a2.w += v2.w;
        a3.x += v3.x; a3.y += v3.y; a3.z += v3.z; a3.w += v3.w;
    }
    for (; e < end; e++) {
        const int s0 = __ldg(&g_col[e]);
        const float4 v0 = *(const float4*)&g_ui[s0 * HID + c];
        a0.x += v0.x; a0.y += v0.y; a0.z += v0.z; a0.w += v0.w;
    }
    float4 s;
    s.x = (a0.x + a1.x) + (a2.x + a3.x);
    s.y = (a0.y + a1.y) + (a2.y + a3.y);
    s.z = (a0.z + a1.z) + (a2.z + a3.z);
    s.w = (a0.w + a1.w) + (a2.w + a3.w);

    if (store_u) *(float4*)&g_u[node * HID + c] = s;

    const float4 xi = *(const float4*)&g_xi[node * HID + c];
    float4 o;
    o.x = fmaxf(xi.x + s.x, 0.f);
    o.y = fmaxf(xi.y + s.y, 0.f);
    o.z = fmaxf(xi.z + s.z, 0.f);
    o.w = fmaxf(xi.w + s.w, 0.f);
    *(float4*)&g_x[node * HID + c] = o;
}

// ---------------- zero pooling/stats scratch ----------------
__global__ __launch_bounds__(256) void zero_aux_kernel() {
    const int i = blockIdx.x * 256 + threadIdx.x;   // 32 blocks -> 8192 threads
    if (i < NG * HID) g_ug[i] = 0.f;
    if (i < 2 * HID)  g_stats[i] = 0.f;
    if (i < 2)        g_wfb[i] = 0.f;
}

// ---------------- per-graph pooling: ug[g] = sum over nodes of u ----------
__global__ __launch_bounds__(256) void graphsum_kernel() {
    const int g = blockIdx.x >> 2;
    const int chunk = blockIdx.x & 3;
    const int col = threadIdx.x & 127;
    const int half = threadIdx.x >> 7;
    const int base = g * NPG + chunk * 256 + half;
    float s = 0.f;
    #pragma unroll 8
    for (int r = 0; r < 256; r += 2)
        s += g_u[(base + r) * HID + col];
    atomicAdd(&g_ug[g * HID + col], s);
}

// ---------------- column stats of x (sum, sumsq) ----------------
__global__ __launch_bounds__(256) void stats_kernel() {
    const int col = threadIdx.x & 127;
    const int half = threadIdx.x >> 7;
    const int base = blockIdx.x * 256 + half;      // 256 blocks x 256 rows
    float s = 0.f, sq = 0.f;
    #pragma unroll 8
    for (int r = 0; r < 256; r += 2) {
        const float v = g_x[(base + r) * HID + col];
        s += v; sq += v * v;
    }
    atomicAdd(&g_stats[col], s);
    atomicAdd(&g_stats[HID + col], sq);
}

// ---------------- fold BatchNorm into final weights ----------------
__global__ __launch_bounds__(256) void fold_kernel(
    const float* __restrict__ gamma, const float* __restrict__ beta,
    const float* __restrict__ Wf, const float* __restrict__ bf)
{
    const int c = threadIdx.x;  // 256 channels
    float mean, var;
    if (c < HID) {
        const float s = g_stats[c], sq = g_stats[HID + c];
        mean = s * (1.f / NN);
        var = sq * (1.f / NN) - mean * mean;
    } else {
        // channels 128..255: graph-level stats of ug, two-pass (avoids
        // E[x^2]-m^2 cancellation: ug values have mean >> std)
        float s = 0.f;
        for (int g = 0; g < NG; g++) s += g_ug[g * HID + (c - HID)];
        mean = s * (1.f / NG);
        float sq = 0.f;
        for (int g = 0; g < NG; g++) {
            const float d = g_ug[g * HID + (c - HID)] - mean;
            sq += d * d;
        }
        var = sq * (1.f / NG);
    }
    const float a = gamma[c] * rsqrtf(var + 1e-5f);
    const float sh = beta[c] - mean * a;
    const float w0 = Wf[2 * c], w1 = Wf[2 * c + 1];
    g_wf2[2 * c] = a * w0;
    g_wf2[2 * c + 1] = a * w1;
    atomicAdd(&g_wfb[0], sh * w0);
    atomicAdd(&g_wfb[1], sh * w1);
    if (c == 0) { atomicAdd(&g_wfb[0], bf[0]); atomicAdd(&g_wfb[1], bf[1]); }
}

// ---------------- final: out[r] = concat(x[r], ug[graph]) @ wf2 + wfb ----
__global__ __launch_bounds__(256) void final_kernel(float* __restrict__ out) {
    __shared__ float sw[2 * HID * 2 + 2];
    const int tid = threadIdx.x;
    sw[2 * tid] = g_wf2[2 * tid];
    sw[2 * tid + 1] = g_wf2[2 * tid + 1];
    if (tid < 2) sw[512 + tid] = g_wfb[tid];
    __syncthreads();

    const int warp = tid >> 5, lane = tid & 31;
    const int row = blockIdx.x * 8 + warp;   // NN/8 blocks
    const float* xr = g_x + (size_t)row * HID;
    const float* ur = g_ug + (size_t)(row >> 10) * HID;

    float a0 = 0.f, a1 = 0.f;
    #pragma unroll
    for (int j = 0; j < 4; j++) {
        const int c = lane + 32 * j;
        const float z = xr[c];
        a0 += z * sw[2 * c];
        a1 += z * sw[2 * c + 1];
    }
    #pragma unroll
    for (int j = 0; j < 4; j++) {
        const int c = lane + 32 * j;
        const float z = ur[c];
        a0 += z * sw[2 * (HID + c)];
        a1 += z * sw[2 * (HID + c) + 1];
    }
    #pragma unroll
    for (int off = 16; off > 0; off >>= 1) {
        a0 += __shfl_xor_sync(0xffffffffu, a0, off);
        a1 += __shfl_xor_sync(0xffffffffu, a1, off);
    }
    if (lane == 0) {
        out[row * 2]     = a0 + sw[512];
        out[row * 2 + 1] = a1 + sw[513];
    }
}

// ---------------- launch ----------------
extern "C" void kernel_launch(void* const* d_in, const int* in_sizes, int n_in,
                              void* d_out, int out_size)
{
    const float* x_in  = (const float*)d_in[0];
    const int*   ei    = (const int*)  d_in[1];
    // d_in[2] = n_nodes (constant 1024, hardcoded)
    const float* Wp    = (const float*)d_in[3];
    const float* bp    = (const float*)d_in[4];
    const float* Wl    = (const float*)d_in[5];
    const float* bl    = (const float*)d_in[6];
    const float* Wa    = (const float*)d_in[7];
    const float* ba    = (const float*)d_in[8];
    const float* gamma = (const float*)d_in[9];
    const float* beta  = (const float*)d_in[10];
    const float* Wf    = (const float*)d_in[11];
    const float* bf    = (const float*)d_in[12];
    float* out = (float*)d_out;

    const int E = in_sizes[1] / 2;

    const int SMEM_DUAL = (2 * HID * HID + 32 * HID) * (int)sizeof(float); // 147456
    cudaFuncSetAttribute(gemm_dual_kernel,
                         cudaFuncAttributeMaxDynamicSharedMemorySize, SMEM_DUAL);

    // CSR build (coalesced scan pipeline)
    zero_cnt_kernel<<<64, 256>>>();
    hist_kernel<<<(E + 255) / 256, 256>>>(ei, E);
    partsum_kernel<<<64, 256>>>();
    scanpart_kernel<<<1, 64>>>();
    localscan_kernel<<<64, 256>>>();
    fill_kernel<<<(E + 255) / 256, 256>>>(ei, E);

    zero_aux_kernel<<<32, 256>>>();
    gemm_proj_kernel<<<148, 256>>>(x_in, Wp, bp);

    for (int i = 0; i < NLAY; i++) {
        gemm_dual_kernel<<<148, 256, SMEM_DUAL>>>(
            Wl + i * HID * HID, bl + i * HID,
            Wa + i * HID * HID, ba + i * HID);
        aggregate_kernel<<<NN / 8, 256>>>(i == NLAY - 1 ? 1 : 0);
    }

    graphsum_kernel<<<NG * 4, 256>>>();
    stats_kernel<<<NN / 256, 256>>>();
    fold_kernel<<<1, 256>>>(gamma, beta, Wf, bf);
    final_kernel<<<NN / 8, 256>>>(out);
}

// round 8
// speedup vs baseline: 1.3850x; 1.1352x over previous
#include <cuda_runtime.h>

// Problem constants (fixed by setup_inputs)
#define NN   65536      // total nodes
#define EIN  64         // input dim
#define HID  128        // hidden dim
#define NE   524288     // edges
#define NG   64         // graphs
#define NPG  1024       // nodes per graph
#define NLAY 3

typedef unsigned long long u64;

// ---------------- persistent device scratch ----------------
__device__ float g_x [NN * HID];   // current activations
__device__ float g_xi[NN * HID];   // self branch
__device__ float g_ui[NN * HID];   // aggr branch (messages)
__device__ float g_u [NN * HID];   // last layer's aggregation (pooling)
__device__ float g_ug[NG * HID];
__device__ float g_stats[2 * HID];   // [0:128) col-sum of x, [128:256) col-sumsq
__device__ float g_wf2[2 * HID * 2]; // BN-folded final weights [256][2]
__device__ float g_wfb[2];           // BN-folded final bias

// CSR (by destination node), rebuilt every launch
__device__ int g_cnt[NN + 1];    // counts -> row_ptr
__device__ int g_cursor[NN];     // fill cursors
__device__ int g_col[NE];        // src node per edge, bucketed by dst
__device__ int g_part[64];       // block partial sums -> exclusive prefixes

// ---------------- f32x2 packed-FMA helpers ----------------
__device__ __forceinline__ u64 pack2(float lo, float hi) {
    u64 r; asm("mov.b64 %0, {%1, %2};" : "=l"(r) : "f"(lo), "f"(hi)); return r;
}
__device__ __forceinline__ void unpack2(u64 v, float& lo, float& hi) {
    asm("mov.b64 {%0, %1}, %2;" : "=f"(lo), "=f"(hi) : "l"(v));
}
__device__ __forceinline__ u64 ffma2(u64 a, u64 b, u64 c) {
    u64 d; asm("fma.rn.f32x2 %0, %1, %2, %3;" : "=l"(d) : "l"(a), "l"(b), "l"(c)); return d;
}

// ================= CSR construction (coalesced 3-stage scan) =================
__global__ __launch_bounds__(256) void zero_cnt_kernel() {   // 64 blocks
    ((int4*)g_cnt)[blockIdx.x * 256 + threadIdx.x] = make_int4(0, 0, 0, 0);
}

__global__ __launch_bounds__(256) void hist_kernel(const int* __restrict__ ei, int E) {
    const int e = blockIdx.x * 256 + threadIdx.x;
    if (e < E) atomicAdd(&g_cnt[__ldg(&ei[E + e])], 1);
}

// 64 blocks: each sums 1024 contiguous counts (coalesced int4)
__global__ __launch_bounds__(256) void partsum_kernel() {
    __shared__ int red[256];
    const int4 v = ((const int4*)g_cnt)[blockIdx.x * 256 + threadIdx.x];
    red[threadIdx.x] = v.x + v.y + v.z + v.w;
    __syncthreads();
    for (int off = 128; off > 0; off >>= 1) {
        if (threadIdx.x < off) red[threadIdx.x] += red[threadIdx.x + off];
        __syncthreads();
    }
    if (threadIdx.x == 0) g_part[blockIdx.x] = red[0];
}

// 1 block, 64 threads: exclusive scan of the 64 partials
__global__ __launch_bounds__(64) void scanpart_kernel() {
    __shared__ int sp[64];
    const int t = threadIdx.x;
    const int v = g_part[t];
    sp[t] = v;
    __syncthreads();
    for (int off = 1; off < 64; off <<= 1) {
        const int u = (t >= off) ? sp[t - off] : 0;
        __syncthreads();
        sp[t] += u;
        __syncthreads();
    }
    g_part[t] = sp[t] - v;            // exclusive prefix
    if (t == 63) g_cnt[NN] = sp[63];  // total edge count
}

// 64 blocks: local exclusive scan over 1024 counts, write row_ptr + cursor
__global__ __launch_bounds__(256) void localscan_kernel() {
    __shared__ int wsum[8];
    const int b = blockIdx.x, t = threadIdx.x;
    const int w = t >> 5, lane = t & 31;
    const int4 c = ((const int4*)g_cnt)[b * 256 + t];
    const int ts = c.x + c.y + c.z + c.w;
    int incl = ts;
    #pragma unroll
    for (int off = 1; off < 32; off <<= 1) {
        const int u = __shfl_up_sync(0xffffffffu, incl, off);
        if (lane >= off) incl += u;
    }
    if (lane == 31) wsum[w] = incl;
    __syncthreads();
    if (t == 0) {
        int run = 0;
        #pragma unroll
        for (int i = 0; i < 8; i++) { const int tmp = wsum[i]; wsum[i] = run; run += tmp; }
    }
    __syncthreads();
    const int base = g_part[b] + wsum[w] + (incl - ts);
    int4 r;
    r.x = base; r.y = r.x + c.x; r.z = r.y + c.y; r.w = r.z + c.z;
    ((int4*)g_cnt)[b * 256 + t] = r;
    ((int4*)g_cursor)[b * 256 + t] = r;
}

__global__ __launch_bounds__(256) void fill_kernel(const int* __restrict__ ei, int E) {
    const int e = blockIdx.x * 256 + threadIdx.x;
    if (e >= E) return;
    const int src = __ldg(&ei[e]);
    const int dst = __ldg(&ei[E + e]);
    const int slot = atomicAdd(&g_cursor[dst], 1);
    g_col[slot] = src;
}

// ---------------- input projection: x = relu(x_in @ Wp + bp) ----------------
__global__ __launch_bounds__(256) void gemm_proj_kernel(
    const float* __restrict__ xin, const float* __restrict__ Wp,
    const float* __restrict__ bp)
{
    __shared__ float sW[EIN * HID];   // 32 KB
    __shared__ float sX[32 * EIN];    // 8 KB
    const int tid = threadIdx.x;
    const int w = tid >> 5, lane = tid & 31;

    for (int i = tid; i < EIN * HID / 4; i += 256)
        ((float4*)sW)[i] = ((const float4*)Wp)[i];

    const float b0 = bp[2 * lane],      b1 = bp[2 * lane + 1];
    const float b2 = bp[64 + 2 * lane], b3 = bp[65 + 2 * lane];

    for (int chunk = blockIdx.x; chunk < NN / 32; chunk += gridDim.x) {
        const int row0 = chunk * 32;
        __syncthreads();
        for (int i = tid; i < 32 * EIN / 4; i += 256)
            ((float4*)sX)[i] = ((const float4*)(xin + (size_t)row0 * EIN))[i];
        __syncthreads();

        u64 acc[4][2];
        #pragma unroll
        for (int r = 0; r < 4; r++) { acc[r][0] = 0ull; acc[r][1] = 0ull; }

        #pragma unroll
        for (int k = 0; k < EIN; k++) {
            const u64 w0 = *(const u64*)&sW[k * HID + 2 * lane];
            const u64 w1 = *(const u64*)&sW[k * HID + 64 + 2 * lane];
            #pragma unroll
            for (int r = 0; r < 4; r++) {
                const float xv = sX[(w * 4 + r) * EIN + k];
                const u64 xx = pack2(xv, xv);
                acc[r][0] = ffma2(xx, w0, acc[r][0]);
                acc[r][1] = ffma2(xx, w1, acc[r][1]);
            }
        }
        #pragma unroll
        for (int r = 0; r < 4; r++) {
            const int row = row0 + w * 4 + r;
            float2 o;
            unpack2(acc[r][0], o.x, o.y);
            o.x = fmaxf(o.x + b0, 0.f); o.y = fmaxf(o.y + b1, 0.f);
            *(float2*)&g_x[row * HID + 2 * lane] = o;
            unpack2(acc[r][1], o.x, o.y);
            o.x = fmaxf(o.x + b2, 0.f); o.y = fmaxf(o.y + b3, 0.f);
            *(float2*)&g_x[row * HID + 64 + 2 * lane] = o;
        }
    }
}

// ---------------- dual GEMM: xi = x@Wl + bl ; ui = x@Wa + ba ----------------
// 64-row chunks, 8 rows per warp: weight LDS amortized over 2x rows, x fetched
// as one LDS.128 per row per 4 k-steps -> FFMA2-issue-bound (not LDS-bound).
__global__ __launch_bounds__(256) void gemm_dual_kernel(
    const float* __restrict__ Wl, const float* __restrict__ bl,
    const float* __restrict__ Wa, const float* __restrict__ ba)
{
    extern __shared__ float smd[];
    float* sWl = smd;                    // 128*128
    float* sWa = smd + HID * HID;        // 128*128
    float* sX  = smd + 2 * HID * HID;    // 64*128

    const int tid = threadIdx.x;
    const int w = tid >> 5, lane = tid & 31;

    for (int i = tid; i < HID * HID / 4; i += 256) {
        ((float4*)sWl)[i] = ((const float4*)Wl)[i];
        ((float4*)sWa)[i] = ((const float4*)Wa)[i];
    }

    const float bl0 = bl[2 * lane],      bl1 = bl[2 * lane + 1];
    const float bl2 = bl[64 + 2 * lane], bl3 = bl[65 + 2 * lane];
    const float ba0 = ba[2 * lane],      ba1 = ba[2 * lane + 1];
    const float ba2 = ba[64 + 2 * lane], ba3 = ba[65 + 2 * lane];

    for (int chunk = blockIdx.x; chunk < NN / 64; chunk += gridDim.x) {
        const int row0 = chunk * 64;
        __syncthreads();
        for (int i = tid; i < 64 * HID / 4; i += 256)
            ((float4*)sX)[i] = ((const float4*)(g_x + (size_t)row0 * HID))[i];
        __syncthreads();

        u64 accl[8][2], acca[8][2];
        #pragma unroll
        for (int r = 0; r < 8; r++) {
            accl[r][0] = 0ull; accl[r][1] = 0ull;
            acca[r][0] = 0ull; acca[r][1] = 0ull;
        }

        #pragma unroll 4
        for (int k4 = 0; k4 < HID / 4; k4++) {
            float4 xr[8];
            #pragma unroll
            for (int r = 0; r < 8; r++)
                xr[r] = *(const float4*)&sX[(w * 8 + r) * HID + k4 * 4];
            #pragma unroll
            for (int kk = 0; kk < 4; kk++) {
                const int k = k4 * 4 + kk;
                const u64 wl0 = *(const u64*)&sWl[k * HID + 2 * lane];
                const u64 wl1 = *(const u64*)&sWl[k * HID + 64 + 2 * lane];
                const u64 wa0 = *(const u64*)&sWa[k * HID + 2 * lane];
                const u64 wa1 = *(const u64*)&sWa[k * HID + 64 + 2 * lane];
                #pragma unroll
                for (int r = 0; r < 8; r++) {
                    const float xv = (kk == 0) ? xr[r].x : (kk == 1) ? xr[r].y
                                   : (kk == 2) ? xr[r].z : xr[r].w;
                    const u64 xx = pack2(xv, xv);
                    accl[r][0] = ffma2(xx, wl0, accl[r][0]);
                    accl[r][1] = ffma2(xx, wl1, accl[r][1]);
                    acca[r][0] = ffma2(xx, wa0, acca[r][0]);
                    acca[r][1] = ffma2(xx, wa1, acca[r][1]);
                }
            }
        }
        #pragma unroll
        for (int r = 0; r < 8; r++) {
            const int row = row0 + w * 8 + r;
            float2 o;
            unpack2(accl[r][0], o.x, o.y); o.x += bl0; o.y += bl1;
            *(float2*)&g_xi[row * HID + 2 * lane] = o;
            unpack2(accl[r][1], o.x, o.y); o.x += bl2; o.y += bl3;
            *(float2*)&g_xi[row * HID + 64 + 2 * lane] = o;
            unpack2(acca[r][0], o.x, o.y); o.x += ba0; o.y += ba1;
            *(float2*)&g_ui[row * HID + 2 * lane] = o;
            unpack2(acca[r][1], o.x, o.y); o.x += ba2; o.y += ba3;
            *(float2*)&g_ui[row * HID + 64 + 2 * lane] = o;
        }
    }
}

// ---------------- CSR-gather aggregation + fused combine (MLP=4) -----------
__global__ __launch_bounds__(256) void aggregate_kernel(int store_u)
{
    const int warp = threadIdx.x >> 5, lane = threadIdx.x & 31;
    const int node = blockIdx.x * 8 + warp;       // grid = NN/8
    const int start = __ldg(&g_cnt[node]);
    const int end   = __ldg(&g_cnt[node + 1]);
    const int c = lane * 4;

    float4 a0 = make_float4(0.f, 0.f, 0.f, 0.f);
    float4 a1 = make_float4(0.f, 0.f, 0.f, 0.f);
    float4 a2 = make_float4(0.f, 0.f, 0.f, 0.f);
    float4 a3 = make_float4(0.f, 0.f, 0.f, 0.f);

    int e = start;
    for (; e + 4 <= end; e += 4) {
        const int s0 = __ldg(&g_col[e]);
        const int s1 = __ldg(&g_col[e + 1]);
        const int s2 = __ldg(&g_col[e + 2]);
        const int s3 = __ldg(&g_col[e + 3]);
        const float4 v0 = *(const float4*)&g_ui[s0 * HID + c];
        const float4 v1 = *(const float4*)&g_ui[s1 * HID + c];
        const float4 v2 = *(const float4*)&g_ui[s2 * HID + c];
        const float4 v3 = *(const float4*)&g_ui[s3 * HID + c];
        a0.x += v0.x; a0.y += v0.y; a0.z += v0.z; a0.w += v0.w;
        a1.x += v1.x; a1.y += v1.y; a1.z += v1.z; a1.w += v1.w;
        a2.x += v2.x; a2.y += v2.y; a2.z += v2.z; a2.w += v2.w;
        a3.x += v3.x; a3.y += v3.y; a3.z += v3.z; a3.w += v3.w;
    }
    for (; e < end; e++) {
        const int s0 = __ldg(&g_col[e]);
        const float4 v0 = *(const float4*)&g_ui[s0 * HID + c];
        a0.x += v0.x; a0.y += v0.y; a0.z += v0.z; a0.w += v0.w;
    }
    float4 s;
    s.x = (a0.x + a1.x) + (a2.x + a3.x);
    s.y = (a0.y + a1.y) + (a2.y + a3.y);
    s.z = (a0.z + a1.z) + (a2.z + a3.z);
    s.w = (a0.w + a1.w) + (a2.w + a3.w);

    if (store_u) *(float4*)&g_u[node * HID + c] = s;

    const float4 xi = *(const float4*)&g_xi[node * HID + c];
    float4 o;
    o.x = fmaxf(xi.x + s.x, 0.f);
    o.y = fmaxf(xi.y + s.y, 0.f);
    o.z = fmaxf(xi.z + s.z, 0.f);
    o.w = fmaxf(xi.w + s.w, 0.f);
    *(float4*)&g_x[node * HID + c] = o;
}

// ---------------- zero pooling/stats scratch ----------------
__global__ __launch_bounds__(256) void zero_aux_kernel() {
    const int i = blockIdx.x * 256 + threadIdx.x;   // 32 blocks -> 8192 threads
    if (i < NG * HID) g_ug[i] = 0.f;
    if (i < 2 * HID)  g_stats[i] = 0.f;
    if (i < 2)        g_wfb[i] = 0.f;
}

// ---------------- per-graph pooling: ug[g] = sum over nodes of u ----------
__global__ __launch_bounds__(256) void graphsum_kernel() {
    const int g = blockIdx.x >> 2;
    const int chunk = blockIdx.x & 3;
    const int col = threadIdx.x & 127;
    const int half = threadIdx.x >> 7;
    const int base = g * NPG + chunk * 256 + half;
    float s = 0.f;
    #pragma unroll 8
    for (int r = 0; r < 256; r += 2)
        s += g_u[(base + r) * HID + col];
    atomicAdd(&g_ug[g * HID + col], s);
}

// ---------------- column stats of x (sum, sumsq) ----------------
__global__ __launch_bounds__(256) void stats_kernel() {
    const int col = threadIdx.x & 127;
    const int half = threadIdx.x >> 7;
    const int base = blockIdx.x * 256 + half;      // 256 blocks x 256 rows
    float s = 0.f, sq = 0.f;
    #pragma unroll 8
    for (int r = 0; r < 256; r += 2) {
        const float v = g_x[(base + r) * HID + col];
        s += v; sq += v * v;
    }
    atomicAdd(&g_stats[col], s);
    atomicAdd(&g_stats[HID + col], sq);
}

// ---------------- fold BatchNorm into final weights ----------------
__global__ __launch_bounds__(256) void fold_kernel(
    const float* __restrict__ gamma, const float* __restrict__ beta,
    const float* __restrict__ Wf, const float* __restrict__ bf)
{
    const int c = threadIdx.x;  // 256 channels
    float mean, var;
    if (c < HID) {
        const float s = g_stats[c], sq = g_stats[HID + c];
        mean = s * (1.f / NN);
        var = sq * (1.f / NN) - mean * mean;
    } else {
        // channels 128..255: graph-level stats of ug, two-pass (avoids
        // E[x^2]-m^2 cancellation: ug values have mean >> std)
        float s = 0.f;
        for (int g = 0; g < NG; g++) s += g_ug[g * HID + (c - HID)];
        mean = s * (1.f / NG);
        float sq = 0.f;
        for (int g = 0; g < NG; g++) {
            const float d = g_ug[g * HID + (c - HID)] - mean;
            sq += d * d;
        }
        var = sq * (1.f / NG);
    }
    const float a = gamma[c] * rsqrtf(var + 1e-5f);
    const float sh = beta[c] - mean * a;
    const float w0 = Wf[2 * c], w1 = Wf[2 * c + 1];
    g_wf2[2 * c] = a * w0;
    g_wf2[2 * c + 1] = a * w1;
    atomicAdd(&g_wfb[0], sh * w0);
    atomicAdd(&g_wfb[1], sh * w1);
    if (c == 0) { atomicAdd(&g_wfb[0], bf[0]); atomicAdd(&g_wfb[1], bf[1]); }
}

// ---------------- final: out[r] = concat(x[r], ug[graph]) @ wf2 + wfb ----
__global__ __launch_bounds__(256) void final_kernel(float* __restrict__ out) {
    __shared__ float sw[2 * HID * 2 + 2];
    const int tid = threadIdx.x;
    sw[2 * tid] = g_wf2[2 * tid];
    sw[2 * tid + 1] = g_wf2[2 * tid + 1];
    if (tid < 2) sw[512 + tid] = g_wfb[tid];
    __syncthreads();

    const int warp = tid >> 5, lane = tid & 31;
    const int row = blockIdx.x * 8 + warp;   // NN/8 blocks
    const float* xr = g_x + (size_t)row * HID;
    const float* ur = g_ug + (size_t)(row >> 10) * HID;

    float a0 = 0.f, a1 = 0.f;
    #pragma unroll
    for (int j = 0; j < 4; j++) {
        const int c = lane + 32 * j;
        const float z = xr[c];
        a0 += z * sw[2 * c];
        a1 += z * sw[2 * c + 1];
    }
    #pragma unroll
    for (int j = 0; j < 4; j++) {
        const int c = lane + 32 * j;
        const float z = ur[c];
        a0 += z * sw[2 * (HID + c)];
        a1 += z * sw[2 * (HID + c) + 1];
    }
    #pragma unroll
    for (int off = 16; off > 0; off >>= 1) {
        a0 += __shfl_xor_sync(0xffffffffu, a0, off);
        a1 += __shfl_xor_sync(0xffffffffu, a1, off);
    }
    if (lane == 0) {
        out[row * 2]     = a0 + sw[512];
        out[row * 2 + 1] = a1 + sw[513];
    }
}

// ---------------- launch ----------------
extern "C" void kernel_launch(void* const* d_in, const int* in_sizes, int n_in,
                              void* d_out, int out_size)
{
    const float* x_in  = (const float*)d_in[0];
    const int*   ei    = (const int*)  d_in[1];
    // d_in[2] = n_nodes (constant 1024, hardcoded)
    const float* Wp    = (const float*)d_in[3];
    const float* bp    = (const float*)d_in[4];
    const float* Wl    = (const float*)d_in[5];
    const float* bl    = (const float*)d_in[6];
    const float* Wa    = (const float*)d_in[7];
    const float* ba    = (const float*)d_in[8];
    const float* gamma = (const float*)d_in[9];
    const float* beta  = (const float*)d_in[10];
    const float* Wf    = (const float*)d_in[11];
    const float* bf    = (const float*)d_in[12];
    float* out = (float*)d_out;

    const int E = in_sizes[1] / 2;

    const int SMEM_DUAL = (2 * HID * HID + 64 * HID) * (int)sizeof(float); // 163840
    cudaFuncSetAttribute(gemm_dual_kernel,
                         cudaFuncAttributeMaxDynamicSharedMemorySize, SMEM_DUAL);

    // CSR build (coalesced scan pipeline)
    zero_cnt_kernel<<<64, 256>>>();
    hist_kernel<<<(E + 255) / 256, 256>>>(ei, E);
    partsum_kernel<<<64, 256>>>();
    scanpart_kernel<<<1, 64>>>();
    localscan_kernel<<<64, 256>>>();
    fill_kernel<<<(E + 255) / 256, 256>>>(ei, E);

    zero_aux_kernel<<<32, 256>>>();
    gemm_proj_kernel<<<148, 256>>>(x_in, Wp, bp);

    for (int i = 0; i < NLAY; i++) {
        gemm_dual_kernel<<<148, 256, SMEM_DUAL>>>(
            Wl + i * HID * HID, bl + i * HID,
            Wa + i * HID * HID, ba + i * HID);
        aggregate_kernel<<<NN / 8, 256>>>(i == NLAY - 1 ? 1 : 0);
    }

    graphsum_kernel<<<NG * 4, 256>>>();
    stats_kernel<<<NN / 256, 256>>>();
    fold_kernel<<<1, 256>>>(gamma, beta, Wf, bf);
    final_kernel<<<NN / 8, 256>>>(out);
}

// round 11
// speedup vs baseline: 1.4878x; 1.0742x over previous
#include <cuda_runtime.h>
#include <cstdint>

// Problem constants (fixed by setup_inputs)
#define NN   65536      // total nodes
#define EIN  64         // input dim
#define HID  128        // hidden dim
#define NE   524288     // edges
#define NG   64         // graphs
#define NPG  1024       // nodes per graph
#define NLAY 3

typedef unsigned long long u64;

// ---------------- persistent device scratch ----------------
__device__ float g_x [NN * HID];   // current activations
__device__ float g_xi[NN * HID];   // self branch
__device__ float g_ui[NN * HID];   // aggr branch (messages)
__device__ float g_u [NN * HID];   // last layer's aggregation (pooling)
__device__ float g_ug[NG * HID];
__device__ float g_stats[2 * HID];
__device__ float g_wf2[2 * HID * 2];
__device__ float g_wfb[2];

// CSR (by destination node), rebuilt every launch
__device__ int g_cnt[NN + 1];
__device__ int g_cursor[NN];
__device__ int g_col[NE];
__device__ int g_part[64];

// ---------------- PDL helpers ----------------
__device__ __forceinline__ void pdl_wait() {
#if __CUDA_ARCH__ >= 900
    cudaGridDependencySynchronize();
#endif
}
__device__ __forceinline__ void pdl_trigger() {
#if __CUDA_ARCH__ >= 900
    cudaTriggerProgrammaticLaunchCompletion();
#endif
}

// ---------------- f32x2 packed-FMA helpers ----------------
__device__ __forceinline__ u64 pack2(float lo, float hi) {
    u64 r; asm("mov.b64 %0, {%1, %2};" : "=l"(r) : "f"(lo), "f"(hi)); return r;
}
__device__ __forceinline__ void unpack2(u64 v, float& lo, float& hi) {
    asm("mov.b64 {%0, %1}, %2;" : "=f"(lo), "=f"(hi) : "l"(v));
}
__device__ __forceinline__ u64 ffma2(u64 a, u64 b, u64 c) {
    u64 d; asm("fma.rn.f32x2 %0, %1, %2, %3;" : "=l"(d) : "l"(a), "l"(b), "l"(c)); return d;
}

// ================= merged zeroing =================
__global__ __launch_bounds__(256) void zero_all_kernel() {   // 64 blocks
    pdl_wait();          // previous replay fully drained
    pdl_trigger();
    const int i = blockIdx.x * 256 + threadIdx.x;
    ((int4*)g_cnt)[i] = make_int4(0, 0, 0, 0);               // 65536 ints
    if (i < NG * HID / 4) ((float4*)g_ug)[i] = make_float4(0.f, 0.f, 0.f, 0.f);
    if (i < 2 * HID / 4)  ((float4*)g_stats)[i] = make_float4(0.f, 0.f, 0.f, 0.f);
    if (i < 2)            g_wfb[i] = 0.f;
}

// ================= CSR construction =================
__global__ __launch_bounds__(256) void hist_kernel(const int* __restrict__ ei, int E) {
    pdl_wait();
    pdl_trigger();
    const int e = blockIdx.x * 256 + threadIdx.x;
    if (e < E) atomicAdd(&g_cnt[__ldg(&ei[E + e])], 1);
}

__global__ __launch_bounds__(256) void partsum_kernel() {
    pdl_wait();
    pdl_trigger();
    __shared__ int red[256];
    const int4 v = ((const int4*)g_cnt)[blockIdx.x * 256 + threadIdx.x];
    red[threadIdx.x] = v.x + v.y + v.z + v.w;
    __syncthreads();
    for (int off = 128; off > 0; off >>= 1) {
        if (threadIdx.x < off) red[threadIdx.x] += red[threadIdx.x + off];
        __syncthreads();
    }
    if (threadIdx.x == 0) g_part[blockIdx.x] = red[0];
}

__global__ __launch_bounds__(64) void scanpart_kernel() {
    pdl_wait();
    pdl_trigger();
    __shared__ int sp[64];
    const int t = threadIdx.x;
    const int v = g_part[t];
    sp[t] = v;
    __syncthreads();
    for (int off = 1; off < 64; off <<= 1) {
        const int u = (t >= off) ? sp[t - off] : 0;
        __syncthreads();
        sp[t] += u;
        __syncthreads();
    }
    g_part[t] = sp[t] - v;
    if (t == 63) g_cnt[NN] = sp[63];
}

__global__ __launch_bounds__(256) void localscan_kernel() {
    pdl_wait();
    pdl_trigger();
    __shared__ int wsum[8];
    const int b = blockIdx.x, t = threadIdx.x;
    const int w = t >> 5, lane = t & 31;
    const int4 c = ((const int4*)g_cnt)[b * 256 + t];
    const int ts = c.x + c.y + c.z + c.w;
    int incl = ts;
    #pragma unroll
    for (int off = 1; off < 32; off <<= 1) {
        const int u = __shfl_up_sync(0xffffffffu, incl, off);
        if (lane >= off) incl += u;
    }
    if (lane == 31) wsum[w] = incl;
    __syncthreads();
    if (t == 0) {
        int run = 0;
        #pragma unroll
        for (int i = 0; i < 8; i++) { const int tmp = wsum[i]; wsum[i] = run; run += tmp; }
    }
    __syncthreads();
    const int base = g_part[b] + wsum[w] + (incl - ts);
    int4 r;
    r.x = base; r.y = r.x + c.x; r.z = r.y + c.y; r.w = r.z + c.z;
    ((int4*)g_cnt)[b * 256 + t] = r;
    ((int4*)g_cursor)[b * 256 + t] = r;
}

__global__ __launch_bounds__(256) void fill_kernel(const int* __restrict__ ei, int E) {
    pdl_wait();
    pdl_trigger();
    const int e = blockIdx.x * 256 + threadIdx.x;
    if (e >= E) return;
    const int src = __ldg(&ei[e]);
    const int dst = __ldg(&ei[E + e]);
    const int slot = atomicAdd(&g_cursor[dst], 1);
    g_col[slot] = src;
}

// ---------------- input projection: x = relu(x_in @ Wp + bp) ----------------
__global__ __launch_bounds__(256) void gemm_proj_kernel(
    const float* __restrict__ xin, const float* __restrict__ Wp,
    const float* __restrict__ bp)
{
    __shared__ float sW[EIN * HID];   // 32 KB
    __shared__ float sX[32 * EIN];    // 8 KB
    const int tid = threadIdx.x;
    const int w = tid >> 5, lane = tid & 31;

    // preamble: weights + biases are harness inputs (never written) -> pre-wait
    for (int i = tid; i < EIN * HID / 4; i += 256)
        ((float4*)sW)[i] = ((const float4*)Wp)[i];
    const float b0 = bp[2 * lane],      b1 = bp[2 * lane + 1];
    const float b2 = bp[64 + 2 * lane], b3 = bp[65 + 2 * lane];

    pdl_wait();
    pdl_trigger();

    for (int chunk = blockIdx.x; chunk < NN / 32; chunk += gridDim.x) {
        const int row0 = chunk * 32;
        __syncthreads();
        for (int i = tid; i < 32 * EIN / 4; i += 256)
            ((float4*)sX)[i] = ((const float4*)(xin + (size_t)row0 * EIN))[i];
        __syncthreads();

        u64 acc[4][2];
        #pragma unroll
        for (int r = 0; r < 4; r++) { acc[r][0] = 0ull; acc[r][1] = 0ull; }

        #pragma unroll
        for (int k = 0; k < EIN; k++) {
            const u64 w0 = *(const u64*)&sW[k * HID + 2 * lane];
            const u64 w1 = *(const u64*)&sW[k * HID + 64 + 2 * lane];
            #pragma unroll
            for (int r = 0; r < 4; r++) {
                const float xv = sX[(w * 4 + r) * EIN + k];
                const u64 xx = pack2(xv, xv);
                acc[r][0] = ffma2(xx, w0, acc[r][0]);
                acc[r][1] = ffma2(xx, w1, acc[r][1]);
            }
        }
        #pragma unroll
        for (int r = 0; r < 4; r++) {
            const int row = row0 + w * 4 + r;
            float2 o;
            unpack2(acc[r][0], o.x, o.y);
            o.x = fmaxf(o.x + b0, 0.f); o.y = fmaxf(o.y + b1, 0.f);
            *(float2*)&g_x[row * HID + 2 * lane] = o;
            unpack2(acc[r][1], o.x, o.y);
            o.x = fmaxf(o.x + b2, 0.f); o.y = fmaxf(o.y + b3, 0.f);
            *(float2*)&g_x[row * HID + 64 + 2 * lane] = o;
        }
    }
}

// ---------------- dual GEMM: xi = x@Wl + bl ; ui = x@Wa + ba ----------------
// 64-row chunks, 8 rows per warp (R8 winner). Weight smem fill pre-wait.
__global__ __launch_bounds__(256) void gemm_dual_kernel(
    const float* __restrict__ Wl, const float* __restrict__ bl,
    const float* __restrict__ Wa, const float* __restrict__ ba)
{
    extern __shared__ float smd[];
    float* sWl = smd;                    // 128*128
    float* sWa = smd + HID * HID;        // 128*128
    float* sX  = smd + 2 * HID * HID;    // 64*128

    const int tid = threadIdx.x;
    const int w = tid >> 5, lane = tid & 31;

    // preamble: weights/biases are harness inputs -> safe before the PDL wait
    for (int i = tid; i < HID * HID / 4; i += 256) {
        ((float4*)sWl)[i] = ((const float4*)Wl)[i];
        ((float4*)sWa)[i] = ((const float4*)Wa)[i];
    }
    const float bl0 = bl[2 * lane],      bl1 = bl[2 * lane + 1];
    const float bl2 = bl[64 + 2 * lane], bl3 = bl[65 + 2 * lane];
    const float ba0 = ba[2 * lane],      ba1 = ba[2 * lane + 1];
    const float ba2 = ba[64 + 2 * lane], ba3 = ba[65 + 2 * lane];

    pdl_wait();
    pdl_trigger();

    for (int chunk = blockIdx.x; chunk < NN / 64; chunk += gridDim.x) {
        const int row0 = chunk * 64;
        __syncthreads();
        for (int i = tid; i < 64 * HID / 4; i += 256)
            ((float4*)sX)[i] = ((const float4*)(g_x + (size_t)row0 * HID))[i];
        __syncthreads();

        u64 accl[8][2], acca[8][2];
        #pragma unroll
        for (int r = 0; r < 8; r++) {
            accl[r][0] = 0ull; accl[r][1] = 0ull;
            acca[r][0] = 0ull; acca[r][1] = 0ull;
        }

        #pragma unroll 4
        for (int k4 = 0; k4 < HID / 4; k4++) {
            float4 xr[8];
            #pragma unroll
            for (int r = 0; r < 8; r++)
                xr[r] = *(const float4*)&sX[(w * 8 + r) * HID + k4 * 4];
            #pragma unroll
            for (int kk = 0; kk < 4; kk++) {
                const int k = k4 * 4 + kk;
                const u64 wl0 = *(const u64*)&sWl[k * HID + 2 * lane];
                const u64 wl1 = *(const u64*)&sWl[k * HID + 64 + 2 * lane];
                const u64 wa0 = *(const u64*)&sWa[k * HID + 2 * lane];
                const u64 wa1 = *(const u64*)&sWa[k * HID + 64 + 2 * lane];
                #pragma unroll
                for (int r = 0; r < 8; r++) {
                    const float xv = (kk == 0) ? xr[r].x : (kk == 1) ? xr[r].y
                                   : (kk == 2) ? xr[r].z : xr[r].w;
                    const u64 xx = pack2(xv, xv);
                    accl[r][0] = ffma2(xx, wl0, accl[r][0]);
                    accl[r][1] = ffma2(xx, wl1, accl[r][1]);
                    acca[r][0] = ffma2(xx, wa0, acca[r][0]);
                    acca[r][1] = ffma2(xx, wa1, acca[r][1]);
                }
            }
        }
        #pragma unroll
        for (int r = 0; r < 8; r++) {
            const int row = row0 + w * 8 + r;
            float2 o;
            unpack2(accl[r][0], o.x, o.y); o.x += bl0; o.y += bl1;
            *(float2*)&g_xi[row * HID + 2 * lane] = o;
            unpack2(accl[r][1], o.x, o.y); o.x += bl2; o.y += bl3;
            *(float2*)&g_xi[row * HID + 64 + 2 * lane] = o;
            unpack2(acca[r][0], o.x, o.y); o.x += ba0; o.y += ba1;
            *(float2*)&g_ui[row * HID + 2 * lane] = o;
            unpack2(acca[r][1], o.x, o.y); o.x += ba2; o.y += ba3;
            *(float2*)&g_ui[row * HID + 64 + 2 * lane] = o;
        }
    }
}

// ---------------- CSR-gather aggregation + fused combine (MLP=4) -----------
__global__ __launch_bounds__(256) void aggregate_kernel(int store_u)
{
    pdl_wait();
    pdl_trigger();
    const int warp = threadIdx.x >> 5, lane = threadIdx.x & 31;
    const int node = blockIdx.x * 8 + warp;       // grid = NN/8
    const int start = __ldg(&g_cnt[node]);
    const int end   = __ldg(&g_cnt[node + 1]);
    const int c = lane * 4;

    float4 a0 = make_float4(0.f, 0.f, 0.f, 0.f);
    float4 a1 = make_float4(0.f, 0.f, 0.f, 0.f);
    float4 a2 = make_float4(0.f, 0.f, 0.f, 0.f);
    float4 a3 = make_float4(0.f, 0.f, 0.f, 0.f);

    int e = start;
    for (; e + 4 <= end; e += 4) {
        const int s0 = __ldg(&g_col[e]);
        const int s1 = __ldg(&g_col[e + 1]);
        const int s2 = __ldg(&g_col[e + 2]);
        const int s3 = __ldg(&g_col[e + 3]);
        const float4 v0 = *(const float4*)&g_ui[s0 * HID + c];
        const float4 v1 = *(const float4*)&g_ui[s1 * HID + c];
        const float4 v2 = *(const float4*)&g_ui[s2 * HID + c];
        const float4 v3 = *(const float4*)&g_ui[s3 * HID + c];
        a0.x += v0.x; a0.y += v0.y; a0.z += v0.z; a0.w += v0.w;
        a1.x += v1.x; a1.y += v1.y; a1.z += v1.z; a1.w += v1.w;
        a2.x += v2.x; a2.y += v2.y; a2.z += v2.z; a2.w += v2.w;
        a3.x += v3.x; a3.y += v3.y; a3.z += v3.z; a3.w += v3.w;
    }
    for (; e < end; e++) {
        const int s0 = __ldg(&g_col[e]);
        const float4 v0 = *(const float4*)&g_ui[s0 * HID + c];
        a0.x += v0.x; a0.y += v0.y; a0.z += v0.z; a0.w += v0.w;
    }
    float4 s;
    s.x = (a0.x + a1.x) + (a2.x + a3.x);
    s.y = (a0.y + a1.y) + (a2.y + a3.y);
    s.z = (a0.z + a1.z) + (a2.z + a3.z);
    s.w = (a0.w + a1.w) + (a2.w + a3.w);

    if (store_u) *(float4*)&g_u[node * HID + c] = s;

    const float4 xi = *(const float4*)&g_xi[node * HID + c];
    float4 o;
    o.x = fmaxf(xi.x + s.x, 0.f);
    o.y = fmaxf(xi.y + s.y, 0.f);
    o.z = fmaxf(xi.z + s.z, 0.f);
    o.w = fmaxf(xi.w + s.w, 0.f);
    *(float4*)&g_x[node * HID + c] = o;
}

// ---------------- merged stats (x col-sum/sumsq) + per-graph pooling -------
__global__ __launch_bounds__(256) void stats_graphsum_kernel() {
    pdl_wait();
    pdl_trigger();
    const int col = threadIdx.x & 127;
    const int half = threadIdx.x >> 7;
    if (blockIdx.x < 256) {
        // column stats of x: 256 blocks x 256 rows
        const int base = blockIdx.x * 256 + half;
        float s = 0.f, sq = 0.f;
        #pragma unroll 8
        for (int r = 0; r < 256; r += 2) {
            const float v = g_x[(base + r) * HID + col];
            s += v; sq += v * v;
        }
        atomicAdd(&g_stats[col], s);
        atomicAdd(&g_stats[HID + col], sq);
    } else {
        // graph pooling of u: 256 blocks (4 per graph)
        const int b = blockIdx.x - 256;
        const int g = b >> 2;
        const int chunk = b & 3;
        const int base = g * NPG + chunk * 256 + half;
        float s = 0.f;
        #pragma unroll 8
        for (int r = 0; r < 256; r += 2)
            s += g_u[(base + r) * HID + col];
        atomicAdd(&g_ug[g * HID + col], s);
    }
}

// ---------------- fold BatchNorm into final weights ----------------
__global__ __launch_bounds__(256) void fold_kernel(
    const float* __restrict__ gamma, const float* __restrict__ beta,
    const float* __restrict__ Wf, const float* __restrict__ bf)
{
    pdl_wait();
    pdl_trigger();
    const int c = threadIdx.x;
    float mean, var;
    if (c < HID) {
        const float s = g_stats[c], sq = g_stats[HID + c];
        mean = s * (1.f / NN);
        var = sq * (1.f / NN) - mean * mean;
    } else {
        float s = 0.f;
        for (int g = 0; g < NG; g++) s += g_ug[g * HID + (c - HID)];
        mean = s * (1.f / NG);
        float sq = 0.f;
        for (int g = 0; g < NG; g++) {
            const float d = g_ug[g * HID + (c - HID)] - mean;
            sq += d * d;
        }
        var = sq * (1.f / NG);
    }
    const float a = gamma[c] * rsqrtf(var + 1e-5f);
    const float sh = beta[c] - mean * a;
    const float w0 = Wf[2 * c], w1 = Wf[2 * c + 1];
    g_wf2[2 * c] = a * w0;
    g_wf2[2 * c + 1] = a * w1;
    atomicAdd(&g_wfb[0], sh * w0);
    atomicAdd(&g_wfb[1], sh * w1);
    if (c == 0) { atomicAdd(&g_wfb[0], bf[0]); atomicAdd(&g_wfb[1], bf[1]); }
}

// ---------------- final projection ----------------
__global__ __launch_bounds__(256) void final_kernel(float* __restrict__ out) {
    pdl_wait();
    pdl_trigger();
    __shared__ float sw[2 * HID * 2 + 2];
    const int tid = threadIdx.x;
    sw[2 * tid] = g_wf2[2 * tid];
    sw[2 * tid + 1] = g_wf2[2 * tid + 1];
    if (tid < 2) sw[512 + tid] = g_wfb[tid];
    __syncthreads();

    const int warp = tid >> 5, lane = tid & 31;
    const int row = blockIdx.x * 8 + warp;
    const float* xr = g_x + (size_t)row * HID;
    const float* ur = g_ug + (size_t)(row >> 10) * HID;

    float a0 = 0.f, a1 = 0.f;
    #pragma unroll
    for (int j = 0; j < 4; j++) {
        const int c = lane + 32 * j;
        const float z = xr[c];
        a0 += z * sw[2 * c];
        a1 += z * sw[2 * c + 1];
    }
    #pragma unroll
    for (int j = 0; j < 4; j++) {
        const int c = lane + 32 * j;
        const float z = ur[c];
        a0 += z * sw[2 * (HID + c)];
        a1 += z * sw[2 * (HID + c) + 1];
    }
    #pragma unroll
    for (int off = 16; off > 0; off >>= 1) {
        a0 += __shfl_xor_sync(0xffffffffu, a0, off);
        a1 += __shfl_xor_sync(0xffffffffu, a1, off);
    }
    if (lane == 0) {
        out[row * 2]     = a0 + sw[512];
        out[row * 2 + 1] = a1 + sw[513];
    }
}

// ---------------- PDL launch helper ----------------
template <typename Kern, typename... Args>
static inline void launch_pdl(Kern k, int grid, int block, size_t smem, Args... args) {
    cudaLaunchConfig_t cfg{};
    cfg.gridDim = dim3(grid, 1, 1);
    cfg.blockDim = dim3(block, 1, 1);
    cfg.dynamicSmemBytes = smem;
    cfg.stream = 0;
    cudaLaunchAttribute at[1];
    at[0].id = cudaLaunchAttributeProgrammaticStreamSerialization;
    at[0].val.programmaticStreamSerializationAllowed = 1;
    cfg.attrs = at;
    cfg.numAttrs = 1;
    cudaLaunchKernelEx(&cfg, k, args...);
}

// ---------------- launch ----------------
extern "C" void kernel_launch(void* const* d_in, const int* in_sizes, int n_in,
                              void* d_out, int out_size)
{
    const float* x_in  = (const float*)d_in[0];
    const int*   ei    = (const int*)  d_in[1];
    // d_in[2] = n_nodes (constant 1024, hardcoded)
    const float* Wp    = (const float*)d_in[3];
    const float* bp    = (const float*)d_in[4];
    const float* Wl    = (const float*)d_in[5];
    const float* bl    = (const float*)d_in[6];
    const float* Wa    = (const float*)d_in[7];
    const float* ba    = (const float*)d_in[8];
    const float* gamma = (const float*)d_in[9];
    const float* beta  = (const float*)d_in[10];
    const float* Wf    = (const float*)d_in[11];
    const float* bf    = (const float*)d_in[12];
    float* out = (float*)d_out;

    const int E = in_sizes[1] / 2;

    const int SMEM_DUAL = (2 * HID * HID + 64 * HID) * (int)sizeof(float); // 163840
    cudaFuncSetAttribute(gemm_dual_kernel,
                         cudaFuncAttributeMaxDynamicSharedMemorySize, SMEM_DUAL);

    // Order chosen so gemm_dual (layer 0) is the 4th launch -> ncu captures it.
    launch_pdl(zero_all_kernel, 64, 256, 0);                                   // 1
    launch_pdl(gemm_proj_kernel, 148, 256, 0, x_in, Wp, bp);                   // 2
    launch_pdl(hist_kernel, (E + 255) / 256, 256, 0, ei, E);                   // 3
    launch_pdl(gemm_dual_kernel, 148, 256, (size_t)SMEM_DUAL,
               Wl, bl, Wa, ba);                                                // 4 (profiled)
    launch_pdl(partsum_kernel, 64, 256, 0);                                    // 5
    launch_pdl(scanpart_kernel, 1, 64, 0);                                     // 6
    launch_pdl(localscan_kernel, 64, 256, 0);                                  // 7
    launch_pdl(fill_kernel, (E + 255) / 256, 256, 0, ei, E);                   // 8
    launch_pdl(aggregate_kernel, NN / 8, 256, 0, 0);                           // 9  (layer 0)

    for (int i = 1; i < NLAY; i++) {
        launch_pdl(gemm_dual_kernel, 148, 256, (size_t)SMEM_DUAL,
                   Wl + i * HID * HID, bl + i * HID,
                   Wa + i * HID * HID, ba + i * HID);
        launch_pdl(aggregate_kernel, NN / 8, 256, 0, i == NLAY - 1 ? 1 : 0);
    }

    launch_pdl(stats_graphsum_kernel, 512, 256, 0);
    launch_pdl(fold_kernel, 1, 256, 0, gamma, beta, Wf, bf);
    launch_pdl(final_kernel, NN / 8, 256, 0, out);
}